// round 7
// baseline (speedup 1.0000x reference)
#include <cuda_runtime.h>

#define N_MAX 100000
#define HID 64
#define V_MAX 16384

// ---- persistent scratch (no allocation allowed) ----
__device__ int    g_outdeg[N_MAX];
__device__ int    g_indeg[N_MAX];
__device__ float  g_nsrc[N_MAX];
__device__ float  g_v[HID];        // W0 W1 W2 wreg
__device__ float  g_c0, g_c1, g_c2;
__device__ float  g_tdot[V_MAX];   // emb_table . v
__device__ float2 g_P[N_MAX];      // prescaled (value, ones) pair
__device__ float2 g_A[N_MAX];      // float2 accumulator
__device__ float  g_Ps[N_MAX];     // prescaled scalar (final prop)
__device__ float  g_s1[N_MAX];     // S^1 1
__device__ float2 g_fin[N_MAX];    // packed {ndst, gid-as-int}

// vector reduction (sm_90+): one RED for the (value, ones) pair
#define RED2(addr, a, b) \
    asm volatile("red.global.add.v2.f32 [%0], {%1, %2};" \
                 :: "l"(addr), "f"(a), "f"(b) : "memory")
#define RED1(addr, a) \
    asm volatile("red.global.add.f32 [%0], %1;" \
                 :: "l"(addr), "f"(a) : "memory")

// ---------------------------------------------------------------
// K1: init + fold. Block 0 folds weights; all blocks zero degrees/out.
// ---------------------------------------------------------------
__global__ void k_init_fold(const float* __restrict__ Ws, const float* __restrict__ bs,
                            const float* __restrict__ wreg,
                            float* out, int n, int ng) {
    int i = blockIdx.x * blockDim.x + threadIdx.x;
    if (i < n) { g_outdeg[i] = 0; g_indeg[i] = 0; }
    if (i < ng) out[i] = 0.0f;

    if (blockIdx.x == 0 && threadIdx.x < HID) {
        __shared__ float sa[HID], sb[HID];
        int k = threadIdx.x;
        float s = 0.f;
        #pragma unroll 8
        for (int j = 0; j < HID; j++) s += Ws[2 * HID * HID + k * HID + j] * wreg[j];
        sa[k] = s;
        __syncwarp();
        if (k == 0) { /* ensure all 64 written: need block sync across 2 warps */ }
        __syncthreads();
        s = 0.f;
        #pragma unroll 8
        for (int j = 0; j < HID; j++) s += Ws[1 * HID * HID + k * HID + j] * sa[j];
        sb[k] = s;
        __syncthreads();
        s = 0.f;
        #pragma unroll 8
        for (int j = 0; j < HID; j++) s += Ws[0 * HID * HID + k * HID + j] * sb[j];
        g_v[k] = s;
        if (k == 0) {
            float c2 = 0.f, c1 = 0.f, c0 = 0.f;
            #pragma unroll 8
            for (int j = 0; j < HID; j++) {
                c2 += bs[2 * HID + j] * wreg[j];
                c1 += bs[1 * HID + j] * sa[j];
                c0 += bs[0 * HID + j] * sb[j];
            }
            g_c2 = c2; g_c1 = c1; g_c0 = c0;
        }
    } else if (blockIdx.x == 0) {
        __syncthreads();   // match block-0 barriers
        __syncthreads();
    }
}

// ---------------------------------------------------------------
// K2: degree counts, 4 edges/thread
// ---------------------------------------------------------------
__global__ void k_deg(const int* __restrict__ src, const int* __restrict__ dst, int e) {
    int i = (blockIdx.x * blockDim.x + threadIdx.x) * 4;
    if (i + 3 < e) {
        int4 s = *(const int4*)&src[i];
        int4 d = *(const int4*)&dst[i];
        atomicAdd(&g_outdeg[s.x], 1); atomicAdd(&g_outdeg[s.y], 1);
        atomicAdd(&g_outdeg[s.z], 1); atomicAdd(&g_outdeg[s.w], 1);
        atomicAdd(&g_indeg[d.x], 1);  atomicAdd(&g_indeg[d.y], 1);
        atomicAdd(&g_indeg[d.z], 1);  atomicAdd(&g_indeg[d.w], 1);
    } else {
        for (; i < e; i++) {
            atomicAdd(&g_outdeg[src[i]], 1);
            atomicAdd(&g_indeg[dst[i]], 1);
        }
    }
}

// ---------------------------------------------------------------
// K3: tdot[w] = emb[w] . v   (16 lanes per vocab word)
// ---------------------------------------------------------------
__global__ void k_tdot(const float* __restrict__ emb, int vocab) {
    int t = blockIdx.x * blockDim.x + threadIdx.x;
    int w = t >> 4;
    int l = t & 15;
    if (w >= vocab) return;
    float4 ev = __ldg((const float4*)emb + w * 16 + l);
    float4 vv = *(const float4*)&g_v[l * 4];
    float p = ev.x * vv.x + ev.y * vv.y + ev.z * vv.z + ev.w * vv.w;
    p += __shfl_xor_sync(0xffffffffu, p, 8);
    p += __shfl_xor_sync(0xffffffffu, p, 4);
    p += __shfl_xor_sync(0xffffffffu, p, 2);
    p += __shfl_xor_sync(0xffffffffu, p, 1);
    if (l == 0) g_tdot[w] = p;
}

// ---------------------------------------------------------------
// K4: norms + P0 = (z0, 1)*nsrc + zero A + pack fin = {ndst, gid}
// ---------------------------------------------------------------
__global__ void k_p0(const int* __restrict__ feats, const int* __restrict__ gid, int n) {
    int i = blockIdx.x * blockDim.x + threadIdx.x;
    if (i >= n) return;
    float ns = rsqrtf(fmaxf((float)g_outdeg[i], 1.0f));
    float nd = rsqrtf(fmaxf((float)g_indeg[i], 1.0f));
    g_nsrc[i] = ns;
    float2 fin;
    fin.x = nd;
    *(int*)&fin.y = gid[i];
    g_fin[i] = fin;
    float z0 = __ldg(&g_tdot[feats[i]]);
    g_P[i] = make_float2(z0 * ns, ns);
    g_A[i] = make_float2(0.f, 0.f);
}

// ---------------------------------------------------------------
// K5: float2 scatter propagation via vector RED (4 edges/thread)
// ---------------------------------------------------------------
__global__ void k_prop2(const int* __restrict__ src, const int* __restrict__ dst, int e) {
    int i = (blockIdx.x * blockDim.x + threadIdx.x) * 4;
    if (i + 3 < e) {
        int4 s = *(const int4*)&src[i];
        int4 d = *(const int4*)&dst[i];
        float2 p0 = __ldg(&g_P[s.x]);
        float2 p1 = __ldg(&g_P[s.y]);
        float2 p2 = __ldg(&g_P[s.z]);
        float2 p3 = __ldg(&g_P[s.w]);
        RED2(&g_A[d.x], p0.x, p0.y);
        RED2(&g_A[d.y], p1.x, p1.y);
        RED2(&g_A[d.z], p2.x, p2.y);
        RED2(&g_A[d.w], p3.x, p3.y);
    } else {
        for (; i < e; i++) {
            float2 p = __ldg(&g_P[src[i]]);
            RED2(&g_A[dst[i]], p.x, p.y);
        }
    }
}

// ---------------------------------------------------------------
// K6: rescale after prop1: U1 = A*nd; s1 = U1.y; P = U1*ns; A = 0
// ---------------------------------------------------------------
__global__ void k_rescale1(int n) {
    int i = blockIdx.x * blockDim.x + threadIdx.x;
    if (i >= n) return;
    float2 A = g_A[i];
    float nd = g_fin[i].x, ns = g_nsrc[i];
    float u = A.x * nd, ss = A.y * nd;
    g_s1[i] = ss;
    g_P[i] = make_float2(u * ns, ss * ns);
    g_A[i] = make_float2(0.f, 0.f);
}

// ---------------------------------------------------------------
// K7: rescale after prop2 + node bias terms scattered to pooled out
//   s2 = A.y*nd; Ps = A.x*nd*ns; out[gid] += c0*s2 + c1*s1 + c2
// ---------------------------------------------------------------
__global__ void k_rescale2(float* __restrict__ out, int n) {
    int i = blockIdx.x * blockDim.x + threadIdx.x;
    if (i >= n) return;
    float2 A = g_A[i];
    float2 fin = g_fin[i];
    float nd = fin.x, ns = g_nsrc[i];
    float u = A.x * nd, s2 = A.y * nd;
    g_Ps[i] = u * ns;
    float nodeterm = g_c0 * s2 + g_c1 * g_s1[i] + g_c2;
    RED1(&out[*(int*)&fin.y], nodeterm);
}

// ---------------------------------------------------------------
// K8: final prop fused with pooling: out[gid[dst]] += Ps[src]*ndst[dst]
// ---------------------------------------------------------------
__global__ void k_prop_out(const int* __restrict__ src, const int* __restrict__ dst,
                           float* __restrict__ out, int e) {
    int i = (blockIdx.x * blockDim.x + threadIdx.x) * 4;
    if (i + 3 < e) {
        int4 s = *(const int4*)&src[i];
        int4 d = *(const int4*)&dst[i];
        float p0 = __ldg(&g_Ps[s.x]);
        float p1 = __ldg(&g_Ps[s.y]);
        float p2 = __ldg(&g_Ps[s.z]);
        float p3 = __ldg(&g_Ps[s.w]);
        float2 f0 = __ldg(&g_fin[d.x]);
        float2 f1 = __ldg(&g_fin[d.y]);
        float2 f2 = __ldg(&g_fin[d.z]);
        float2 f3 = __ldg(&g_fin[d.w]);
        RED1(&out[*(int*)&f0.y], p0 * f0.x);
        RED1(&out[*(int*)&f1.y], p1 * f1.x);
        RED1(&out[*(int*)&f2.y], p2 * f2.x);
        RED1(&out[*(int*)&f3.y], p3 * f3.x);
    } else {
        for (; i < e; i++) {
            float p = __ldg(&g_Ps[src[i]]);
            float2 f = __ldg(&g_fin[dst[i]]);
            RED1(&out[*(int*)&f.y], p * f.x);
        }
    }
}

// ---------------------------------------------------------------
extern "C" void kernel_launch(void* const* d_in, const int* in_sizes, int n_in,
                              void* d_out, int out_size)
{
    const int* feats = (const int*)d_in[0];
    const int* src   = (const int*)d_in[1];
    const int* dst   = (const int*)d_in[2];
    const int* gid   = (const int*)d_in[3];
    int k = 4;
    if (n_in >= 9 && in_sizes[4] == 1) k = 5;
    const float* emb  = (const float*)d_in[k];
    const float* Ws   = (const float*)d_in[k + 1];
    const float* bs   = (const float*)d_in[k + 2];
    const float* wreg = (const float*)d_in[k + 3];
    float* out = (float*)d_out;

    int n = in_sizes[0];
    int e = in_sizes[1];
    int ng = out_size;
    int vocab = in_sizes[k] / HID;

    int nB = (n + 255) / 256;
    int eB = (e / 4 + 256) / 256;

    k_init_fold<<<nB, 256>>>(Ws, bs, wreg, out, n, ng);
    k_deg<<<eB, 256>>>(src, dst, e);
    k_tdot<<<(vocab * 16 + 255) / 256, 256>>>(emb, vocab);
    k_p0<<<nB, 256>>>(feats, gid, n);

    k_prop2<<<eB, 256>>>(src, dst, e);       // S^1
    k_rescale1<<<nB, 256>>>(n);
    k_prop2<<<eB, 256>>>(src, dst, e);       // S^2
    k_rescale2<<<nB, 256>>>(out, n);         // + node bias terms -> out
    k_prop_out<<<eB, 256>>>(src, dst, out, e); // S^3 fused with pooling
}

// round 8
// speedup vs baseline: 2.7935x; 2.7935x over previous
#include <cuda_runtime.h>

#define N_MAX 100000
#define HID 64
#define V_MAX 16384

// ---- persistent scratch (no allocation allowed) ----
__device__ int    g_outdeg[N_MAX];
__device__ int    g_indeg[N_MAX];
__device__ float  g_nsrc[N_MAX];
__device__ float  g_ndst[N_MAX];
__device__ float  g_v[HID];        // W0 W1 W2 wreg
__device__ float  g_c0, g_c1, g_c2;
__device__ float  g_tdot[V_MAX];   // emb_table . v
__device__ float2 g_P[N_MAX];      // prescaled (value, ones) pair
__device__ float2 g_A[N_MAX];      // float2 accumulator
__device__ float  g_Ps[N_MAX];     // prescaled scalar (final prop)
__device__ float  g_As[N_MAX];     // scalar accumulator (100k addrs!)
__device__ float  g_s1[N_MAX];     // S^1 1
__device__ float  g_s2[N_MAX];     // S^2 1

// vector RED (sm_90+): one instruction for the (value, ones) pair
#define RED2(addr, a, b) \
    asm volatile("red.global.add.v2.f32 [%0], {%1, %2};" \
                 :: "l"(addr), "f"(a), "f"(b) : "memory")

// ---------------------------------------------------------------
// K1: init + fold. All threads of block 0 run the barrier path.
// ---------------------------------------------------------------
__global__ void k_init_fold(const float* __restrict__ Ws, const float* __restrict__ bs,
                            const float* __restrict__ wreg,
                            float* out, int n, int ng) {
    int i = blockIdx.x * blockDim.x + threadIdx.x;
    if (i < n) { g_outdeg[i] = 0; g_indeg[i] = 0; g_As[i] = 0.f; }
    if (i < ng) out[i] = 0.0f;

    if (blockIdx.x == 0) {
        __shared__ float sa[HID], sb[HID];
        int k = threadIdx.x;
        if (k < HID) {
            float s = 0.f;
            #pragma unroll 8
            for (int j = 0; j < HID; j++) s += Ws[2 * HID * HID + k * HID + j] * wreg[j];
            sa[k] = s;
        }
        __syncthreads();
        if (k < HID) {
            float s = 0.f;
            #pragma unroll 8
            for (int j = 0; j < HID; j++) s += Ws[1 * HID * HID + k * HID + j] * sa[j];
            sb[k] = s;
        }
        __syncthreads();
        if (k < HID) {
            float s = 0.f;
            #pragma unroll 8
            for (int j = 0; j < HID; j++) s += Ws[0 * HID * HID + k * HID + j] * sb[j];
            g_v[k] = s;
        }
        if (k == 0) {
            float c2 = 0.f, c1 = 0.f, c0 = 0.f;
            #pragma unroll 8
            for (int j = 0; j < HID; j++) {
                c2 += bs[2 * HID + j] * wreg[j];
                c1 += bs[1 * HID + j] * sa[j];
                c0 += bs[0 * HID + j] * sb[j];
            }
            g_c2 = c2; g_c1 = c1; g_c0 = c0;
        }
    }
}

// ---------------------------------------------------------------
// K2: degree counts, 4 edges/thread
// ---------------------------------------------------------------
__global__ void k_deg(const int* __restrict__ src, const int* __restrict__ dst, int e) {
    int i = (blockIdx.x * blockDim.x + threadIdx.x) * 4;
    if (i + 3 < e) {
        int4 s = *(const int4*)&src[i];
        int4 d = *(const int4*)&dst[i];
        atomicAdd(&g_outdeg[s.x], 1); atomicAdd(&g_outdeg[s.y], 1);
        atomicAdd(&g_outdeg[s.z], 1); atomicAdd(&g_outdeg[s.w], 1);
        atomicAdd(&g_indeg[d.x], 1);  atomicAdd(&g_indeg[d.y], 1);
        atomicAdd(&g_indeg[d.z], 1);  atomicAdd(&g_indeg[d.w], 1);
    } else {
        for (; i < e; i++) {
            atomicAdd(&g_outdeg[src[i]], 1);
            atomicAdd(&g_indeg[dst[i]], 1);
        }
    }
}

// ---------------------------------------------------------------
// K3: tdot[w] = emb[w] . v   (16 lanes per vocab word)
// ---------------------------------------------------------------
__global__ void k_tdot(const float* __restrict__ emb, int vocab) {
    int t = blockIdx.x * blockDim.x + threadIdx.x;
    int w = t >> 4;
    int l = t & 15;
    if (w >= vocab) return;
    float4 ev = __ldg((const float4*)emb + w * 16 + l);
    float4 vv = *(const float4*)&g_v[l * 4];
    float p = ev.x * vv.x + ev.y * vv.y + ev.z * vv.z + ev.w * vv.w;
    p += __shfl_xor_sync(0xffffffffu, p, 8);
    p += __shfl_xor_sync(0xffffffffu, p, 4);
    p += __shfl_xor_sync(0xffffffffu, p, 2);
    p += __shfl_xor_sync(0xffffffffu, p, 1);
    if (l == 0) g_tdot[w] = p;
}

// ---------------------------------------------------------------
// K4: norms + P0 = (z0, 1)*nsrc + zero A
// ---------------------------------------------------------------
__global__ void k_p0(const int* __restrict__ feats, int n) {
    int i = blockIdx.x * blockDim.x + threadIdx.x;
    if (i >= n) return;
    float ns = rsqrtf(fmaxf((float)g_outdeg[i], 1.0f));
    float nd = rsqrtf(fmaxf((float)g_indeg[i], 1.0f));
    g_nsrc[i] = ns;
    g_ndst[i] = nd;
    float z0 = __ldg(&g_tdot[feats[i]]);
    g_P[i] = make_float2(z0 * ns, ns);
    g_A[i] = make_float2(0.f, 0.f);
}

// ---------------------------------------------------------------
// K5: float2 scatter propagation via vector RED (4 edges/thread)
// targets 100k addresses -> low contention
// ---------------------------------------------------------------
__global__ void k_prop2(const int* __restrict__ src, const int* __restrict__ dst, int e) {
    int i = (blockIdx.x * blockDim.x + threadIdx.x) * 4;
    if (i + 3 < e) {
        int4 s = *(const int4*)&src[i];
        int4 d = *(const int4*)&dst[i];
        float2 p0 = __ldg(&g_P[s.x]);
        float2 p1 = __ldg(&g_P[s.y]);
        float2 p2 = __ldg(&g_P[s.z]);
        float2 p3 = __ldg(&g_P[s.w]);
        RED2(&g_A[d.x], p0.x, p0.y);
        RED2(&g_A[d.y], p1.x, p1.y);
        RED2(&g_A[d.z], p2.x, p2.y);
        RED2(&g_A[d.w], p3.x, p3.y);
    } else {
        for (; i < e; i++) {
            float2 p = __ldg(&g_P[src[i]]);
            RED2(&g_A[dst[i]], p.x, p.y);
        }
    }
}

// ---------------------------------------------------------------
// K6: rescale after prop1: U1 = A*nd; s1 = U1.y; P = U1*ns; A = 0
// ---------------------------------------------------------------
__global__ void k_rescale1(int n) {
    int i = blockIdx.x * blockDim.x + threadIdx.x;
    if (i >= n) return;
    float2 A = g_A[i];
    float nd = g_ndst[i], ns = g_nsrc[i];
    float u = A.x * nd, ss = A.y * nd;
    g_s1[i] = ss;
    g_P[i] = make_float2(u * ns, ss * ns);
    g_A[i] = make_float2(0.f, 0.f);
}

// ---------------------------------------------------------------
// K7: rescale after prop2: s2 = A.y*nd; Ps = A.x*nd*ns
// ---------------------------------------------------------------
__global__ void k_rescale2(int n) {
    int i = blockIdx.x * blockDim.x + threadIdx.x;
    if (i >= n) return;
    float2 A = g_A[i];
    float nd = g_ndst[i], ns = g_nsrc[i];
    g_s2[i] = A.y * nd;
    g_Ps[i] = A.x * nd * ns;
}

// ---------------------------------------------------------------
// K8: final scalar prop: As[dst] += Ps[src]   (100k addrs, low contention)
// ---------------------------------------------------------------
__global__ void k_prop1(const int* __restrict__ src, const int* __restrict__ dst, int e) {
    int i = (blockIdx.x * blockDim.x + threadIdx.x) * 4;
    if (i + 3 < e) {
        int4 s = *(const int4*)&src[i];
        int4 d = *(const int4*)&dst[i];
        float p0 = __ldg(&g_Ps[s.x]);
        float p1 = __ldg(&g_Ps[s.y]);
        float p2 = __ldg(&g_Ps[s.z]);
        float p3 = __ldg(&g_Ps[s.w]);
        atomicAdd(&g_As[d.x], p0);
        atomicAdd(&g_As[d.y], p1);
        atomicAdd(&g_As[d.z], p2);
        atomicAdd(&g_As[d.w], p3);
    } else {
        for (; i < e; i++)
            atomicAdd(&g_As[dst[i]], __ldg(&g_Ps[src[i]]));
    }
}

// ---------------------------------------------------------------
// K9: per-node combine + pooled output (only 100k atomics to 512 addrs)
// ---------------------------------------------------------------
__global__ void k_out(const int* __restrict__ gid, float* __restrict__ out, int n) {
    int i = blockIdx.x * blockDim.x + threadIdx.x;
    if (i >= n) return;
    float val = g_As[i] * g_ndst[i] + g_c0 * g_s2[i] + g_c1 * g_s1[i] + g_c2;
    atomicAdd(&out[gid[i]], val);
}

// ---------------------------------------------------------------
extern "C" void kernel_launch(void* const* d_in, const int* in_sizes, int n_in,
                              void* d_out, int out_size)
{
    const int* feats = (const int*)d_in[0];
    const int* src   = (const int*)d_in[1];
    const int* dst   = (const int*)d_in[2];
    const int* gid   = (const int*)d_in[3];
    int k = 4;
    if (n_in >= 9 && in_sizes[4] == 1) k = 5;
    const float* emb  = (const float*)d_in[k];
    const float* Ws   = (const float*)d_in[k + 1];
    const float* bs   = (const float*)d_in[k + 2];
    const float* wreg = (const float*)d_in[k + 3];
    float* out = (float*)d_out;

    int n = in_sizes[0];
    int e = in_sizes[1];
    int ng = out_size;
    int vocab = in_sizes[k] / HID;

    int nB = (n + 255) / 256;
    int eB = (e / 4 + 256) / 256;

    k_init_fold<<<nB, 256>>>(Ws, bs, wreg, out, n, ng);
    k_deg<<<eB, 256>>>(src, dst, e);
    k_tdot<<<(vocab * 16 + 255) / 256, 256>>>(emb, vocab);
    k_p0<<<nB, 256>>>(feats, n);

    k_prop2<<<eB, 256>>>(src, dst, e);     // S^1
    k_rescale1<<<nB, 256>>>(n);
    k_prop2<<<eB, 256>>>(src, dst, e);     // S^2
    k_rescale2<<<nB, 256>>>(n);
    k_prop1<<<eB, 256>>>(src, dst, e);     // S^3 (scalar)
    k_out<<<nB, 256>>>(gid, out, n);
}